// round 1
// baseline (speedup 1.0000x reference)
#include <cuda_runtime.h>
#include <cuda_bf16.h>
#include <math.h>

// Problem constants
#define Bdim 4
#define Sdim 1024
#define Edim 512
#define NHdim 8
#define Ddim 64
#define NTOK (Bdim * Sdim)        // 4096
#define E4 (4 * Edim)             // 2048

// ---------------- scratch (device globals; allocation-free) ----------------
__device__ float g_q[NTOK * Edim];
__device__ float g_k[NTOK * Edim];
__device__ float g_v[NTOK * Edim];
__device__ float g_attn[NTOK * Edim];
__device__ float g_proj[NTOK * Edim];
__device__ float g_body1[NTOK * Edim];
__device__ float g_limb1[NTOK * Edim];
__device__ float g_bcross[NTOK * Edim];
__device__ float g_lcross[NTOK * Edim];
__device__ float g_body2[NTOK * Edim];
__device__ float g_limb2[NTOK * Edim];
__device__ float g_mid[NTOK * E4];

// ---------------- helpers ----------------
__device__ __forceinline__ float read_temp(const void* p) {
    int iv = *(const int*)p;
    float fv = __int_as_float(iv);
    // small positive int bit-patterns are fp32 denormals -> must have been int
    if (iv > 0 && iv < 0x00800000) return (float)iv;
    return fv;
}

__device__ __forceinline__ float block_sum_256(float v, float* red) {
    int t = threadIdx.x;
    red[t] = v;
    __syncthreads();
    #pragma unroll
    for (int s = 128; s > 0; s >>= 1) {
        if (t < s) red[t] += red[t + s];
        __syncthreads();
    }
    float r = red[0];
    __syncthreads();
    return r;
}

// ---------------- GEMM: C[M,N] = A[M,K] @ W[K,N] + bias (+ optional exact GELU) ----------------
// Requires M%128==0, N%128==0, K%8==0. 256 threads, 128x128 tile, 8x8 microtile.
__global__ __launch_bounds__(256) void gemm_bias_act(
    const float* __restrict__ A, const float* __restrict__ W,
    const float* __restrict__ bias, float* __restrict__ C,
    int M, int N, int K, int act)
{
    __shared__ float As[8][128];
    __shared__ float Bs[8][128];

    int tid = threadIdx.x;
    int row0 = blockIdx.y * 128;
    int col0 = blockIdx.x * 128;

    int tr = (tid / 16) * 8;   // 0..120
    int tc = (tid % 16) * 8;   // 0..120

    float acc[8][8];
    #pragma unroll
    for (int i = 0; i < 8; i++)
        #pragma unroll
        for (int j = 0; j < 8; j++) acc[i][j] = 0.f;

    int ar = tid / 2;            // 0..127 : row within A tile
    int ac = (tid % 2) * 4;      // 0 or 4 : k offset
    int br = tid / 32;           // 0..7   : k within B tile
    int bc = (tid % 32) * 4;     // 0..124 : col within B tile

    for (int k0 = 0; k0 < K; k0 += 8) {
        float4 av = *(const float4*)(A + (size_t)(row0 + ar) * K + k0 + ac);
        As[ac + 0][ar] = av.x;
        As[ac + 1][ar] = av.y;
        As[ac + 2][ar] = av.z;
        As[ac + 3][ar] = av.w;
        float4 bv = *(const float4*)(W + (size_t)(k0 + br) * N + col0 + bc);
        *(float4*)&Bs[br][bc] = bv;
        __syncthreads();

        #pragma unroll
        for (int kk = 0; kk < 8; kk++) {
            float a[8], b[8];
            #pragma unroll
            for (int i = 0; i < 4; i++) {
                float4 t0 = *(const float4*)&As[kk][tr + 4 * i];
                a[4 * i + 0] = t0.x; a[4 * i + 1] = t0.y; a[4 * i + 2] = t0.z; a[4 * i + 3] = t0.w;
                float4 t1 = *(const float4*)&Bs[kk][tc + 4 * i];
                b[4 * i + 0] = t1.x; b[4 * i + 1] = t1.y; b[4 * i + 2] = t1.z; b[4 * i + 3] = t1.w;
            }
            #pragma unroll
            for (int i = 0; i < 8; i++)
                #pragma unroll
                for (int j = 0; j < 8; j++)
                    acc[i][j] += a[i] * b[j];
        }
        __syncthreads();
    }

    #pragma unroll
    for (int i = 0; i < 8; i++) {
        float out[8];
        #pragma unroll
        for (int j = 0; j < 8; j++) {
            float v = acc[i][j] + bias[col0 + tc + j];
            if (act == 1) v = 0.5f * v * (1.f + erff(v * 0.70710678118f));
            out[j] = v;
        }
        float* crow = C + (size_t)(row0 + tr + i) * N + col0 + tc;
        *(float4*)(crow)     = make_float4(out[0], out[1], out[2], out[3]);
        *(float4*)(crow + 4) = make_float4(out[4], out[5], out[6], out[7]);
    }
}

// ---------------- Attention: O[b,q,h,:] = softmax(Q K^T * scale) V ----------------
// grid: (B*NH, S/128), block: 128 threads, one thread per query row. Flash-style online softmax.
__global__ __launch_bounds__(128) void attention_kernel(
    const float* __restrict__ Q, const float* __restrict__ K,
    const float* __restrict__ V, float* __restrict__ O,
    const void* __restrict__ temp_ptr)
{
    __shared__ float4 Kt[64][16];   // 64 keys x 64 dims
    __shared__ float4 Vt[64][16];

    int bh = blockIdx.x;
    int b = bh >> 3;
    int h = bh & 7;
    int qrow = blockIdx.y * 128 + threadIdx.x;

    float scale = 0.125f / read_temp(temp_ptr);   // D^-0.5 / temp

    // load q row, pre-scaled
    float q[64];
    {
        const float4* qp = (const float4*)(Q + ((size_t)(b * Sdim + qrow)) * Edim + h * Ddim);
        #pragma unroll
        for (int d = 0; d < 16; d++) {
            float4 t = qp[d];
            q[4 * d + 0] = t.x * scale;
            q[4 * d + 1] = t.y * scale;
            q[4 * d + 2] = t.z * scale;
            q[4 * d + 3] = t.w * scale;
        }
    }

    float m = -1e30f, l = 0.f;
    float o[64];
    #pragma unroll
    for (int d = 0; d < 64; d++) o[d] = 0.f;

    for (int kt = 0; kt < Sdim; kt += 64) {
        for (int idx = threadIdx.x; idx < 64 * 16; idx += 128) {
            int r = idx >> 4, c = idx & 15;
            size_t base = ((size_t)(b * Sdim + kt + r)) * Edim + h * Ddim;
            Kt[r][c] = *(const float4*)(K + base + c * 4);
            Vt[r][c] = *(const float4*)(V + base + c * 4);
        }
        __syncthreads();

        #pragma unroll 2
        for (int j = 0; j < 64; j++) {
            float s = 0.f;
            #pragma unroll
            for (int d = 0; d < 16; d++) {
                float4 kk = Kt[j][d];
                s += q[4 * d + 0] * kk.x + q[4 * d + 1] * kk.y
                   + q[4 * d + 2] * kk.z + q[4 * d + 3] * kk.w;
            }
            if (s > m) {
                float corr = __expf(m - s);
                l *= corr;
                #pragma unroll
                for (int d = 0; d < 64; d++) o[d] *= corr;
                m = s;
            }
            float p = __expf(s - m);
            l += p;
            #pragma unroll
            for (int d = 0; d < 16; d++) {
                float4 vv = Vt[j][d];
                o[4 * d + 0] += p * vv.x;
                o[4 * d + 1] += p * vv.y;
                o[4 * d + 2] += p * vv.z;
                o[4 * d + 3] += p * vv.w;
            }
        }
        __syncthreads();
    }

    float inv = 1.f / l;
    float* op = O + ((size_t)(b * Sdim + qrow)) * Edim + h * Ddim;
    #pragma unroll
    for (int d = 0; d < 16; d++) {
        *(float4*)(op + 4 * d) = make_float4(o[4 * d + 0] * inv, o[4 * d + 1] * inv,
                                             o[4 * d + 2] * inv, o[4 * d + 3] * inv);
    }
}

// ---------------- out = LayerNorm(a + b) * scale + bias ; one block per token ----------------
__global__ __launch_bounds__(256) void add_ln_kernel(
    const float* __restrict__ a, const float* __restrict__ b,
    const float* __restrict__ scale, const float* __restrict__ bias,
    float* __restrict__ out)
{
    __shared__ float red[256];
    int t = threadIdx.x;
    size_t base = (size_t)blockIdx.x * Edim;

    float x0 = a[base + t] + b[base + t];
    float x1 = a[base + 256 + t] + b[base + 256 + t];

    float mu = block_sum_256(x0 + x1, red) * (1.f / Edim);
    float d0 = x0 - mu, d1 = x1 - mu;
    float var = block_sum_256(d0 * d0 + d1 * d1, red) * (1.f / Edim);
    float r = rsqrtf(var + 1e-5f);

    out[base + t]       = d0 * r * scale[t]       + bias[t];
    out[base + 256 + t] = d1 * r * scale[256 + t] + bias[256 + t];
}

// ---------------- gate + mix + LayerNorm; one block per token ----------------
// logits = concat([x, xc]) @ gw + gb; g = softmax(logits); y = LN(x*g0 + xc*g1)
__global__ __launch_bounds__(256) void gate_mix_ln_kernel(
    const float* __restrict__ x, const float* __restrict__ xc,
    const float* __restrict__ gw, const float* __restrict__ gb,
    const float* __restrict__ scale, const float* __restrict__ bias,
    float* __restrict__ out)
{
    __shared__ float red[256];
    int t = threadIdx.x;
    size_t base = (size_t)blockIdx.x * Edim;

    float x0 = x[base + t],        x1 = x[base + 256 + t];
    float c0 = xc[base + t],       c1 = xc[base + 256 + t];

    // gate logits: rows 0..511 of gw pair with x, rows 512..1023 with xc
    float l0 = x0 * gw[t * 2]             + x1 * gw[(256 + t) * 2]
             + c0 * gw[(512 + t) * 2]     + c1 * gw[(768 + t) * 2];
    float l1 = x0 * gw[t * 2 + 1]         + x1 * gw[(256 + t) * 2 + 1]
             + c0 * gw[(512 + t) * 2 + 1] + c1 * gw[(768 + t) * 2 + 1];

    l0 = block_sum_256(l0, red) + gb[0];
    l1 = block_sum_256(l1, red) + gb[1];

    float mx = fmaxf(l0, l1);
    float e0 = __expf(l0 - mx), e1 = __expf(l1 - mx);
    float g0 = e0 / (e0 + e1), g1 = 1.f - g0;

    float m0 = x0 * g0 + c0 * g1;
    float m1 = x1 * g0 + c1 * g1;

    float mu = block_sum_256(m0 + m1, red) * (1.f / Edim);
    float d0 = m0 - mu, d1 = m1 - mu;
    float var = block_sum_256(d0 * d0 + d1 * d1, red) * (1.f / Edim);
    float r = rsqrtf(var + 1e-5f);

    out[base + t]       = d0 * r * scale[t]       + bias[t];
    out[base + 256 + t] = d1 * r * scale[256 + t] + bias[256 + t];
}

// ---------------- host side ----------------
static void launch_gemm(const float* A, const float* W, const float* bias, float* C,
                        int M, int N, int K, int act)
{
    dim3 grid(N / 128, M / 128);
    gemm_bias_act<<<grid, 256>>>(A, W, bias, C, M, N, K, act);
}

extern "C" void kernel_launch(void* const* d_in, const int* in_sizes, int n_in,
                              void* d_out, int out_size)
{
    const float* body_feats = (const float*)d_in[0];
    const float* limb_feats = (const float*)d_in[1];
    const float* qw = (const float*)d_in[2];
    const float* qb = (const float*)d_in[3];
    const float* kw = (const float*)d_in[4];
    const float* kb = (const float*)d_in[5];
    const float* vw = (const float*)d_in[6];
    const float* vb = (const float*)d_in[7];
    const float* ow = (const float*)d_in[8];
    const float* ob = (const float*)d_in[9];
    const float* w1 = (const float*)d_in[10];
    const float* b1 = (const float*)d_in[11];
    const float* w2 = (const float*)d_in[12];
    const float* b2 = (const float*)d_in[13];
    const float* ns = (const float*)d_in[14];
    const float* nb = (const float*)d_in[15];
    const float* gw = (const float*)d_in[16];
    const float* gb = (const float*)d_in[17];
    const void*  temp = d_in[18];

    float *q, *k, *v, *attn, *proj, *body1, *limb1, *bcross, *lcross, *body2, *limb2, *mid;
    cudaGetSymbolAddress((void**)&q, g_q);
    cudaGetSymbolAddress((void**)&k, g_k);
    cudaGetSymbolAddress((void**)&v, g_v);
    cudaGetSymbolAddress((void**)&attn, g_attn);
    cudaGetSymbolAddress((void**)&proj, g_proj);
    cudaGetSymbolAddress((void**)&body1, g_body1);
    cudaGetSymbolAddress((void**)&limb1, g_limb1);
    cudaGetSymbolAddress((void**)&bcross, g_bcross);
    cudaGetSymbolAddress((void**)&lcross, g_lcross);
    cudaGetSymbolAddress((void**)&body2, g_body2);
    cudaGetSymbolAddress((void**)&limb2, g_limb2);
    cudaGetSymbolAddress((void**)&mid, g_mid);

    float* out_body = (float*)d_out;
    float* out_limb = (float*)d_out + (size_t)NTOK * Edim;

    const int EE = Edim * Edim;
    dim3 agrid(Bdim * NHdim, Sdim / 128);

    // ---- self attention: body (i=0) -> body1, limb (i=1) -> limb1 ----
    for (int s = 0; s < 2; s++) {
        int i = s;  // attn index
        const float* xin = (s == 0) ? body_feats : limb_feats;
        float* dst = (s == 0) ? body1 : limb1;
        int nidx = (s == 0) ? 0 : 3;

        launch_gemm(xin, qw + (size_t)i * EE, qb + i * Edim, q, NTOK, Edim, Edim, 0);
        launch_gemm(xin, kw + (size_t)i * EE, kb + i * Edim, k, NTOK, Edim, Edim, 0);
        launch_gemm(xin, vw + (size_t)i * EE, vb + i * Edim, v, NTOK, Edim, Edim, 0);
        attention_kernel<<<agrid, 128>>>(q, k, v, attn, temp);
        launch_gemm(attn, ow + (size_t)i * EE, ob + i * Edim, proj, NTOK, Edim, Edim, 0);
        add_ln_kernel<<<NTOK, 256>>>(xin, proj, ns + nidx * Edim, nb + nidx * Edim, dst);
    }

    // ---- cross attention: i=2 (q=body1, kv=limb1) -> bcross; i=3 (q=limb1, kv=body1) -> lcross ----
    for (int s = 0; s < 2; s++) {
        int i = 2 + s;
        const float* qx = (s == 0) ? body1 : limb1;
        const float* kvx = (s == 0) ? limb1 : body1;
        float* dst = (s == 0) ? bcross : lcross;

        launch_gemm(qx,  qw + (size_t)i * EE, qb + i * Edim, q, NTOK, Edim, Edim, 0);
        launch_gemm(kvx, kw + (size_t)i * EE, kb + i * Edim, k, NTOK, Edim, Edim, 0);
        launch_gemm(kvx, vw + (size_t)i * EE, vb + i * Edim, v, NTOK, Edim, Edim, 0);
        attention_kernel<<<agrid, 128>>>(q, k, v, attn, temp);
        launch_gemm(attn, ow + (size_t)i * EE, ob + i * Edim, dst, NTOK, Edim, Edim, 0);
    }

    // ---- gates + mix + LN (note: norm index 1 for BOTH streams, faithful to reference) ----
    gate_mix_ln_kernel<<<NTOK, 256>>>(body1, bcross, gw, gb, ns + 1 * Edim, nb + 1 * Edim, body2);
    gate_mix_ln_kernel<<<NTOK, 256>>>(limb1, lcross, gw, gb, ns + 1 * Edim, nb + 1 * Edim, limb2);

    // ---- FFN + final LN ----
    // body: ln(2, body2 + gelu(body2@w1[0]+b1[0]) @ w2[0] + b2[0])
    launch_gemm(body2, w1, b1, mid, NTOK, E4, Edim, 1);
    launch_gemm(mid, w2, b2, proj, NTOK, Edim, E4, 0);
    add_ln_kernel<<<NTOK, 256>>>(body2, proj, ns + 2 * Edim, nb + 2 * Edim, out_body);

    // limb: ln(5, limb2 + ffn(1, limb2))
    launch_gemm(limb2, w1 + (size_t)Edim * E4, b1 + E4, mid, NTOK, E4, Edim, 1);
    launch_gemm(mid, w2 + (size_t)E4 * Edim, b2 + Edim, proj, NTOK, Edim, E4, 0);
    add_ln_kernel<<<NTOK, 256>>>(limb2, proj, ns + 5 * Edim, nb + 5 * Edim, out_limb);
}

// round 2
// speedup vs baseline: 1.3822x; 1.3822x over previous
#include <cuda_runtime.h>
#include <cuda_bf16.h>
#include <math.h>

// Problem constants
#define Bdim 4
#define Sdim 1024
#define Edim 512
#define NHdim 8
#define Ddim 64
#define NTOK (Bdim * Sdim)        // 4096
#define E4 (4 * Edim)             // 2048

// ---------------- scratch (device globals; allocation-free) ----------------
__device__ float g_q[NTOK * Edim];
__device__ float g_k[NTOK * Edim];
__device__ float g_v[NTOK * Edim];
__device__ float g_attn[NTOK * Edim];
__device__ float g_proj[NTOK * Edim];
__device__ float g_body1[NTOK * Edim];
__device__ float g_limb1[NTOK * Edim];
__device__ float g_bcross[NTOK * Edim];
__device__ float g_lcross[NTOK * Edim];
__device__ float g_body2[NTOK * Edim];
__device__ float g_limb2[NTOK * Edim];
__device__ float g_mid[NTOK * E4];

// ---------------- helpers ----------------
__device__ __forceinline__ float read_temp(const void* p) {
    int iv = *(const int*)p;
    float fv = __int_as_float(iv);
    if (iv > 0 && iv < 0x00800000) return (float)iv;  // int bit pattern
    return fv;
}

__device__ __forceinline__ unsigned f2tf32(float f) {
    unsigned u;
    asm("cvt.rna.tf32.f32 %0, %1;" : "=r"(u) : "f"(f));
    return u;
}

__device__ __forceinline__ float block_sum_256(float v, float* red) {
    int t = threadIdx.x;
    red[t] = v;
    __syncthreads();
    #pragma unroll
    for (int s = 128; s > 0; s >>= 1) {
        if (t < s) red[t] += red[t + s];
        __syncthreads();
    }
    float r = red[0];
    __syncthreads();
    return r;
}

// ---------------- TF32 GEMM: C[M,N] = A[M,K] @ W[K,N] + bias (+opt GELU) ----------------
// BM=64, BN=128, BK=32. 256 threads = 8 warps (2 along M x 4 along N), warp tile 32x32.
// mma.sync.m16n8k8 tf32. A staged to smem as [m][k] (ld 36), B as [k][n] (ld 136).
#define GBM 64
#define GBN 128
#define GBK 32
#define LDA 36
#define LDB 136

__global__ __launch_bounds__(256) void gemm_tf32(
    const float* __restrict__ A, const float* __restrict__ W,
    const float* __restrict__ bias, float* __restrict__ C,
    int M, int N, int K, int act)
{
    __shared__ float As[GBM][LDA];
    __shared__ float Bs[GBK][LDB];

    int tid = threadIdx.x;
    int lane = tid & 31;
    int warp = tid >> 5;
    int g = lane >> 2;       // group id 0..7
    int tig = lane & 3;      // thread in group 0..3

    int row0 = blockIdx.y * GBM;
    int col0 = blockIdx.x * GBN;

    int wm0 = (warp & 1) * 32;   // warp row offset in tile
    int wn0 = (warp >> 1) * 32;  // warp col offset in tile

    float acc[2][4][4];
    #pragma unroll
    for (int mf = 0; mf < 2; mf++)
        #pragma unroll
        for (int nf = 0; nf < 4; nf++)
            #pragma unroll
            for (int r = 0; r < 4; r++) acc[mf][nf][r] = 0.f;

    // staging assignments
    // A tile: 64 rows x 32 k = 512 float4; 2 per thread
    int a_row[2], a_c4[2];
    #pragma unroll
    for (int it = 0; it < 2; it++) {
        int f = tid + it * 256;
        a_row[it] = f >> 3;       // 8 float4 per row
        a_c4[it] = f & 7;
    }
    // B tile: 32 k x 128 n = 1024 float4; 4 per thread
    int b_k[4], b_c4[4];
    #pragma unroll
    for (int it = 0; it < 4; it++) {
        int f = tid + it * 256;
        b_k[it] = f >> 5;         // 32 float4 per k-row
        b_c4[it] = f & 31;
    }

    float4 areg[2], breg[4];

    // preload tile 0
    #pragma unroll
    for (int it = 0; it < 2; it++)
        areg[it] = *(const float4*)(A + (size_t)(row0 + a_row[it]) * K + a_c4[it] * 4);
    #pragma unroll
    for (int it = 0; it < 4; it++)
        breg[it] = *(const float4*)(W + (size_t)b_k[it] * N + col0 + b_c4[it] * 4);

    int nkt = K / GBK;
    for (int kt = 0; kt < nkt; kt++) {
        // store staged (tf32-rounded) tile to smem
        #pragma unroll
        for (int it = 0; it < 2; it++) {
            float* p = &As[a_row[it]][a_c4[it] * 4];
            p[0] = __uint_as_float(f2tf32(areg[it].x));
            p[1] = __uint_as_float(f2tf32(areg[it].y));
            p[2] = __uint_as_float(f2tf32(areg[it].z));
            p[3] = __uint_as_float(f2tf32(areg[it].w));
        }
        #pragma unroll
        for (int it = 0; it < 4; it++) {
            float* p = &Bs[b_k[it]][b_c4[it] * 4];
            p[0] = __uint_as_float(f2tf32(breg[it].x));
            p[1] = __uint_as_float(f2tf32(breg[it].y));
            p[2] = __uint_as_float(f2tf32(breg[it].z));
            p[3] = __uint_as_float(f2tf32(breg[it].w));
        }
        __syncthreads();

        // prefetch next tile
        if (kt + 1 < nkt) {
            int k0 = (kt + 1) * GBK;
            #pragma unroll
            for (int it = 0; it < 2; it++)
                areg[it] = *(const float4*)(A + (size_t)(row0 + a_row[it]) * K + k0 + a_c4[it] * 4);
            #pragma unroll
            for (int it = 0; it < 4; it++)
                breg[it] = *(const float4*)(W + (size_t)(k0 + b_k[it]) * N + col0 + b_c4[it] * 4);
        }

        // compute: 4 k-steps of 8
        #pragma unroll
        for (int ks = 0; ks < 4; ks++) {
            int kk = ks * 8;
            unsigned a_frag[2][4];
            #pragma unroll
            for (int mf = 0; mf < 2; mf++) {
                int rbase = wm0 + mf * 16;
                a_frag[mf][0] = __float_as_uint(As[rbase + g][kk + tig]);
                a_frag[mf][1] = __float_as_uint(As[rbase + g + 8][kk + tig]);
                a_frag[mf][2] = __float_as_uint(As[rbase + g][kk + tig + 4]);
                a_frag[mf][3] = __float_as_uint(As[rbase + g + 8][kk + tig + 4]);
            }
            unsigned b_frag[4][2];
            #pragma unroll
            for (int nf = 0; nf < 4; nf++) {
                int cbase = wn0 + nf * 8 + g;
                b_frag[nf][0] = __float_as_uint(Bs[kk + tig][cbase]);
                b_frag[nf][1] = __float_as_uint(Bs[kk + tig + 4][cbase]);
            }
            #pragma unroll
            for (int mf = 0; mf < 2; mf++)
                #pragma unroll
                for (int nf = 0; nf < 4; nf++) {
                    asm volatile(
                        "mma.sync.aligned.m16n8k8.row.col.f32.tf32.tf32.f32 "
                        "{%0,%1,%2,%3}, {%4,%5,%6,%7}, {%8,%9}, {%0,%1,%2,%3};\n"
                        : "+f"(acc[mf][nf][0]), "+f"(acc[mf][nf][1]),
                          "+f"(acc[mf][nf][2]), "+f"(acc[mf][nf][3])
                        : "r"(a_frag[mf][0]), "r"(a_frag[mf][1]),
                          "r"(a_frag[mf][2]), "r"(a_frag[mf][3]),
                          "r"(b_frag[nf][0]), "r"(b_frag[nf][1]));
                }
        }
        __syncthreads();
    }

    // epilogue
    #pragma unroll
    for (int mf = 0; mf < 2; mf++) {
        #pragma unroll
        for (int nf = 0; nf < 4; nf++) {
            int col = col0 + wn0 + nf * 8 + tig * 2;
            float bx = bias[col], by = bias[col + 1];
            float v0 = acc[mf][nf][0] + bx;
            float v1 = acc[mf][nf][1] + by;
            float v2 = acc[mf][nf][2] + bx;
            float v3 = acc[mf][nf][3] + by;
            if (act == 1) {
                v0 = 0.5f * v0 * (1.f + erff(v0 * 0.70710678118f));
                v1 = 0.5f * v1 * (1.f + erff(v1 * 0.70710678118f));
                v2 = 0.5f * v2 * (1.f + erff(v2 * 0.70710678118f));
                v3 = 0.5f * v3 * (1.f + erff(v3 * 0.70710678118f));
            }
            int r = row0 + wm0 + mf * 16 + g;
            *(float2*)(C + (size_t)r * N + col) = make_float2(v0, v1);
            *(float2*)(C + (size_t)(r + 8) * N + col) = make_float2(v2, v3);
        }
    }
}

// ---------------- Attention: O[b,q,h,:] = softmax(Q K^T * scale) V ----------------
// grid: (B*NH, S/128), block: 256 threads, 2 threads per query (each owns 32 dims).
__global__ __launch_bounds__(256) void attention_kernel(
    const float* __restrict__ Q, const float* __restrict__ K,
    const float* __restrict__ V, float* __restrict__ O,
    const void* __restrict__ temp_ptr)
{
    __shared__ float4 Kt[64][16];   // 64 keys x 64 dims
    __shared__ float4 Vt[64][16];

    int bh = blockIdx.x;
    int b = bh >> 3;
    int h = bh & 7;
    int tid = threadIdx.x;
    int qrow = blockIdx.y * 128 + (tid >> 1);
    int half = tid & 1;        // which 32-dim half this thread owns
    int c8 = half * 8;         // float4 offset of this half

    float scale = 0.125f / read_temp(temp_ptr);   // D^-0.5 / temp

    float q[32];
    {
        const float4* qp = (const float4*)(Q + ((size_t)(b * Sdim + qrow)) * Edim + h * Ddim + half * 32);
        #pragma unroll
        for (int d = 0; d < 8; d++) {
            float4 t = qp[d];
            q[4 * d + 0] = t.x * scale;
            q[4 * d + 1] = t.y * scale;
            q[4 * d + 2] = t.z * scale;
            q[4 * d + 3] = t.w * scale;
        }
    }

    float m = -1e30f, l = 0.f;
    float o[32];
    #pragma unroll
    for (int d = 0; d < 32; d++) o[d] = 0.f;

    for (int kt = 0; kt < Sdim; kt += 64) {
        #pragma unroll
        for (int it = 0; it < 4; it++) {
            int idx = tid + it * 256;
            int r = idx >> 4, c = idx & 15;
            size_t base = ((size_t)(b * Sdim + kt + r)) * Edim + h * Ddim;
            Kt[r][c] = *(const float4*)(K + base + c * 4);
            Vt[r][c] = *(const float4*)(V + base + c * 4);
        }
        __syncthreads();

        #pragma unroll 2
        for (int j = 0; j < 64; j++) {
            float sp = 0.f;
            #pragma unroll
            for (int d = 0; d < 8; d++) {
                float4 kk = Kt[j][c8 + d];
                sp += q[4 * d + 0] * kk.x + q[4 * d + 1] * kk.y
                    + q[4 * d + 2] * kk.z + q[4 * d + 3] * kk.w;
            }
            float s = sp + __shfl_xor_sync(0xffffffffu, sp, 1);
            if (s > m) {
                float corr = __expf(m - s);
                l *= corr;
                #pragma unroll
                for (int d = 0; d < 32; d++) o[d] *= corr;
                m = s;
            }
            float p = __expf(s - m);
            l += p;
            #pragma unroll
            for (int d = 0; d < 8; d++) {
                float4 vv = Vt[j][c8 + d];
                o[4 * d + 0] += p * vv.x;
                o[4 * d + 1] += p * vv.y;
                o[4 * d + 2] += p * vv.z;
                o[4 * d + 3] += p * vv.w;
            }
        }
        __syncthreads();
    }

    float inv = 1.f / l;
    float* op = O + ((size_t)(b * Sdim + qrow)) * Edim + h * Ddim + half * 32;
    #pragma unroll
    for (int d = 0; d < 8; d++) {
        *(float4*)(op + 4 * d) = make_float4(o[4 * d + 0] * inv, o[4 * d + 1] * inv,
                                             o[4 * d + 2] * inv, o[4 * d + 3] * inv);
    }
}

// ---------------- out = LayerNorm(a + b) * scale + bias ; one block per token ----------------
__global__ __launch_bounds__(256) void add_ln_kernel(
    const float* __restrict__ a, const float* __restrict__ b,
    const float* __restrict__ scale, const float* __restrict__ bias,
    float* __restrict__ out)
{
    __shared__ float red[256];
    int t = threadIdx.x;
    size_t base = (size_t)blockIdx.x * Edim;

    float x0 = a[base + t] + b[base + t];
    float x1 = a[base + 256 + t] + b[base + 256 + t];

    float mu = block_sum_256(x0 + x1, red) * (1.f / Edim);
    float d0 = x0 - mu, d1 = x1 - mu;
    float var = block_sum_256(d0 * d0 + d1 * d1, red) * (1.f / Edim);
    float r = rsqrtf(var + 1e-5f);

    out[base + t]       = d0 * r * scale[t]       + bias[t];
    out[base + 256 + t] = d1 * r * scale[256 + t] + bias[256 + t];
}

// ---------------- gate + mix + LayerNorm; one block per token ----------------
__global__ __launch_bounds__(256) void gate_mix_ln_kernel(
    const float* __restrict__ x, const float* __restrict__ xc,
    const float* __restrict__ gw, const float* __restrict__ gb,
    const float* __restrict__ scale, const float* __restrict__ bias,
    float* __restrict__ out)
{
    __shared__ float red[256];
    int t = threadIdx.x;
    size_t base = (size_t)blockIdx.x * Edim;

    float x0 = x[base + t],        x1 = x[base + 256 + t];
    float c0 = xc[base + t],       c1 = xc[base + 256 + t];

    float l0 = x0 * gw[t * 2]             + x1 * gw[(256 + t) * 2]
             + c0 * gw[(512 + t) * 2]     + c1 * gw[(768 + t) * 2];
    float l1 = x0 * gw[t * 2 + 1]         + x1 * gw[(256 + t) * 2 + 1]
             + c0 * gw[(512 + t) * 2 + 1] + c1 * gw[(768 + t) * 2 + 1];

    l0 = block_sum_256(l0, red) + gb[0];
    l1 = block_sum_256(l1, red) + gb[1];

    float mx = fmaxf(l0, l1);
    float e0 = __expf(l0 - mx), e1 = __expf(l1 - mx);
    float g0 = e0 / (e0 + e1), g1 = 1.f - g0;

    float m0 = x0 * g0 + c0 * g1;
    float m1 = x1 * g0 + c1 * g1;

    float mu = block_sum_256(m0 + m1, red) * (1.f / Edim);
    float d0 = m0 - mu, d1 = m1 - mu;
    float var = block_sum_256(d0 * d0 + d1 * d1, red) * (1.f / Edim);
    float r = rsqrtf(var + 1e-5f);

    out[base + t]       = d0 * r * scale[t]       + bias[t];
    out[base + 256 + t] = d1 * r * scale[256 + t] + bias[256 + t];
}

// ---------------- host side ----------------
static void launch_gemm(const float* A, const float* W, const float* bias, float* C,
                        int M, int N, int K, int act)
{
    dim3 grid(N / GBN, M / GBM);
    gemm_tf32<<<grid, 256>>>(A, W, bias, C, M, N, K, act);
}

extern "C" void kernel_launch(void* const* d_in, const int* in_sizes, int n_in,
                              void* d_out, int out_size)
{
    const float* body_feats = (const float*)d_in[0];
    const float* limb_feats = (const float*)d_in[1];
    const float* qw = (const float*)d_in[2];
    const float* qb = (const float*)d_in[3];
    const float* kw = (const float*)d_in[4];
    const float* kb = (const float*)d_in[5];
    const float* vw = (const float*)d_in[6];
    const float* vb = (const float*)d_in[7];
    const float* ow = (const float*)d_in[8];
    const float* ob = (const float*)d_in[9];
    const float* w1 = (const float*)d_in[10];
    const float* b1 = (const float*)d_in[11];
    const float* w2 = (const float*)d_in[12];
    const float* b2 = (const float*)d_in[13];
    const float* ns = (const float*)d_in[14];
    const float* nb = (const float*)d_in[15];
    const float* gw = (const float*)d_in[16];
    const float* gb = (const float*)d_in[17];
    const void*  temp = d_in[18];

    float *q, *k, *v, *attn, *proj, *body1, *limb1, *bcross, *lcross, *body2, *limb2, *mid;
    cudaGetSymbolAddress((void**)&q, g_q);
    cudaGetSymbolAddress((void**)&k, g_k);
    cudaGetSymbolAddress((void**)&v, g_v);
    cudaGetSymbolAddress((void**)&attn, g_attn);
    cudaGetSymbolAddress((void**)&proj, g_proj);
    cudaGetSymbolAddress((void**)&body1, g_body1);
    cudaGetSymbolAddress((void**)&limb1, g_limb1);
    cudaGetSymbolAddress((void**)&bcross, g_bcross);
    cudaGetSymbolAddress((void**)&lcross, g_lcross);
    cudaGetSymbolAddress((void**)&body2, g_body2);
    cudaGetSymbolAddress((void**)&limb2, g_limb2);
    cudaGetSymbolAddress((void**)&mid, g_mid);

    float* out_body = (float*)d_out;
    float* out_limb = (float*)d_out + (size_t)NTOK * Edim;

    const int EE = Edim * Edim;
    dim3 agrid(Bdim * NHdim, Sdim / 128);

    // ---- self attention: body (i=0) -> body1, limb (i=1) -> limb1 ----
    for (int s = 0; s < 2; s++) {
        int i = s;
        const float* xin = (s == 0) ? body_feats : limb_feats;
        float* dst = (s == 0) ? body1 : limb1;
        int nidx = (s == 0) ? 0 : 3;

        launch_gemm(xin, qw + (size_t)i * EE, qb + i * Edim, q, NTOK, Edim, Edim, 0);
        launch_gemm(xin, kw + (size_t)i * EE, kb + i * Edim, k, NTOK, Edim, Edim, 0);
        launch_gemm(xin, vw + (size_t)i * EE, vb + i * Edim, v, NTOK, Edim, Edim, 0);
        attention_kernel<<<agrid, 256>>>(q, k, v, attn, temp);
        launch_gemm(attn, ow + (size_t)i * EE, ob + i * Edim, proj, NTOK, Edim, Edim, 0);
        add_ln_kernel<<<NTOK, 256>>>(xin, proj, ns + nidx * Edim, nb + nidx * Edim, dst);
    }

    // ---- cross attention ----
    for (int s = 0; s < 2; s++) {
        int i = 2 + s;
        const float* qx = (s == 0) ? body1 : limb1;
        const float* kvx = (s == 0) ? limb1 : body1;
        float* dst = (s == 0) ? bcross : lcross;

        launch_gemm(qx,  qw + (size_t)i * EE, qb + i * Edim, q, NTOK, Edim, Edim, 0);
        launch_gemm(kvx, kw + (size_t)i * EE, kb + i * Edim, k, NTOK, Edim, Edim, 0);
        launch_gemm(kvx, vw + (size_t)i * EE, vb + i * Edim, v, NTOK, Edim, Edim, 0);
        attention_kernel<<<agrid, 256>>>(q, k, v, attn, temp);
        launch_gemm(attn, ow + (size_t)i * EE, ob + i * Edim, dst, NTOK, Edim, Edim, 0);
    }

    // ---- gates + mix + LN (norm index 1 for BOTH streams, faithful to reference) ----
    gate_mix_ln_kernel<<<NTOK, 256>>>(body1, bcross, gw, gb, ns + 1 * Edim, nb + 1 * Edim, body2);
    gate_mix_ln_kernel<<<NTOK, 256>>>(limb1, lcross, gw, gb, ns + 1 * Edim, nb + 1 * Edim, limb2);

    // ---- FFN + final LN ----
    launch_gemm(body2, w1, b1, mid, NTOK, E4, Edim, 1);
    launch_gemm(mid, w2, b2, proj, NTOK, Edim, E4, 0);
    add_ln_kernel<<<NTOK, 256>>>(body2, proj, ns + 2 * Edim, nb + 2 * Edim, out_body);

    launch_gemm(limb2, w1 + (size_t)Edim * E4, b1 + E4, mid, NTOK, E4, Edim, 1);
    launch_gemm(mid, w2 + (size_t)E4 * Edim, b2 + Edim, proj, NTOK, Edim, E4, 0);
    add_ln_kernel<<<NTOK, 256>>>(limb2, proj, ns + 5 * Edim, nb + 5 * Edim, out_limb);
}

// round 3
// speedup vs baseline: 3.2495x; 2.3509x over previous
#include <cuda_runtime.h>
#include <cuda_bf16.h>
#include <math.h>

// Problem constants
#define Bdim 4
#define Sdim 1024
#define Edim 512
#define NHdim 8
#define Ddim 64
#define NTOK (Bdim * Sdim)        // 4096
#define E4 (4 * Edim)             // 2048

// ---------------- scratch (device globals; allocation-free) ----------------
__device__ float g_q[NTOK * Edim];
__device__ float g_k[NTOK * Edim];
__device__ float g_v[NTOK * Edim];
__device__ float g_attn[NTOK * Edim];
__device__ float g_proj[NTOK * Edim];
__device__ float g_body1[NTOK * Edim];
__device__ float g_limb1[NTOK * Edim];
__device__ float g_bcross[NTOK * Edim];
__device__ float g_lcross[NTOK * Edim];
__device__ float g_body2[NTOK * Edim];
__device__ float g_limb2[NTOK * Edim];
__device__ float g_mid[NTOK * E4];

// ---------------- helpers ----------------
__device__ __forceinline__ float read_temp(const void* p) {
    int iv = *(const int*)p;
    float fv = __int_as_float(iv);
    if (iv > 0 && iv < 0x00800000) return (float)iv;  // int bit pattern
    return fv;
}

__device__ __forceinline__ unsigned f2tf32(float f) {
    unsigned u;
    asm("cvt.rna.tf32.f32 %0, %1;" : "=r"(u) : "f"(f));
    return u;
}

__device__ __forceinline__ float tf32f(float f) {
    return __uint_as_float(f2tf32(f));
}

__device__ __forceinline__ float block_sum_256(float v, float* red) {
    int t = threadIdx.x;
    red[t] = v;
    __syncthreads();
    #pragma unroll
    for (int s = 128; s > 0; s >>= 1) {
        if (t < s) red[t] += red[t + s];
        __syncthreads();
    }
    float r = red[0];
    __syncthreads();
    return r;
}

#define MMA_TF32(ACC, AF, B0, B1)                                              \
    asm volatile(                                                              \
        "mma.sync.aligned.m16n8k8.row.col.f32.tf32.tf32.f32 "                  \
        "{%0,%1,%2,%3}, {%4,%5,%6,%7}, {%8,%9}, {%0,%1,%2,%3};\n"              \
        : "+f"((ACC)[0]), "+f"((ACC)[1]), "+f"((ACC)[2]), "+f"((ACC)[3])       \
        : "r"((AF)[0]), "r"((AF)[1]), "r"((AF)[2]), "r"((AF)[3]),              \
          "r"(B0), "r"(B1))

// ---------------- TF32 GEMM: C[M,N] = A[M,K] @ W[K,N] + bias (+opt GELU) ----------------
#define GBM 64
#define GBN 128
#define GBK 32
#define LDA 36
#define LDB 136

__global__ __launch_bounds__(256) void gemm_tf32(
    const float* __restrict__ A, const float* __restrict__ W,
    const float* __restrict__ bias, float* __restrict__ C,
    int M, int N, int K, int act)
{
    __shared__ float As[GBM][LDA];
    __shared__ float Bs[GBK][LDB];

    int tid = threadIdx.x;
    int lane = tid & 31;
    int warp = tid >> 5;
    int g = lane >> 2;
    int tig = lane & 3;

    int row0 = blockIdx.y * GBM;
    int col0 = blockIdx.x * GBN;

    int wm0 = (warp & 1) * 32;
    int wn0 = (warp >> 1) * 32;

    float acc[2][4][4];
    #pragma unroll
    for (int mf = 0; mf < 2; mf++)
        #pragma unroll
        for (int nf = 0; nf < 4; nf++)
            #pragma unroll
            for (int r = 0; r < 4; r++) acc[mf][nf][r] = 0.f;

    int a_row[2], a_c4[2];
    #pragma unroll
    for (int it = 0; it < 2; it++) {
        int f = tid + it * 256;
        a_row[it] = f >> 3;
        a_c4[it] = f & 7;
    }
    int b_k[4], b_c4[4];
    #pragma unroll
    for (int it = 0; it < 4; it++) {
        int f = tid + it * 256;
        b_k[it] = f >> 5;
        b_c4[it] = f & 31;
    }

    float4 areg[2], breg[4];

    #pragma unroll
    for (int it = 0; it < 2; it++)
        areg[it] = *(const float4*)(A + (size_t)(row0 + a_row[it]) * K + a_c4[it] * 4);
    #pragma unroll
    for (int it = 0; it < 4; it++)
        breg[it] = *(const float4*)(W + (size_t)b_k[it] * N + col0 + b_c4[it] * 4);

    int nkt = K / GBK;
    for (int kt = 0; kt < nkt; kt++) {
        #pragma unroll
        for (int it = 0; it < 2; it++) {
            float* p = &As[a_row[it]][a_c4[it] * 4];
            p[0] = tf32f(areg[it].x);
            p[1] = tf32f(areg[it].y);
            p[2] = tf32f(areg[it].z);
            p[3] = tf32f(areg[it].w);
        }
        #pragma unroll
        for (int it = 0; it < 4; it++) {
            float* p = &Bs[b_k[it]][b_c4[it] * 4];
            p[0] = tf32f(breg[it].x);
            p[1] = tf32f(breg[it].y);
            p[2] = tf32f(breg[it].z);
            p[3] = tf32f(breg[it].w);
        }
        __syncthreads();

        if (kt + 1 < nkt) {
            int k0 = (kt + 1) * GBK;
            #pragma unroll
            for (int it = 0; it < 2; it++)
                areg[it] = *(const float4*)(A + (size_t)(row0 + a_row[it]) * K + k0 + a_c4[it] * 4);
            #pragma unroll
            for (int it = 0; it < 4; it++)
                breg[it] = *(const float4*)(W + (size_t)(k0 + b_k[it]) * N + col0 + b_c4[it] * 4);
        }

        #pragma unroll
        for (int ks = 0; ks < 4; ks++) {
            int kk = ks * 8;
            unsigned a_frag[2][4];
            #pragma unroll
            for (int mf = 0; mf < 2; mf++) {
                int rbase = wm0 + mf * 16;
                a_frag[mf][0] = __float_as_uint(As[rbase + g][kk + tig]);
                a_frag[mf][1] = __float_as_uint(As[rbase + g + 8][kk + tig]);
                a_frag[mf][2] = __float_as_uint(As[rbase + g][kk + tig + 4]);
                a_frag[mf][3] = __float_as_uint(As[rbase + g + 8][kk + tig + 4]);
            }
            unsigned b_frag[4][2];
            #pragma unroll
            for (int nf = 0; nf < 4; nf++) {
                int cbase = wn0 + nf * 8 + g;
                b_frag[nf][0] = __float_as_uint(Bs[kk + tig][cbase]);
                b_frag[nf][1] = __float_as_uint(Bs[kk + tig + 4][cbase]);
            }
            #pragma unroll
            for (int mf = 0; mf < 2; mf++)
                #pragma unroll
                for (int nf = 0; nf < 4; nf++)
                    MMA_TF32(acc[mf][nf], a_frag[mf], b_frag[nf][0], b_frag[nf][1]);
        }
        __syncthreads();
    }

    #pragma unroll
    for (int mf = 0; mf < 2; mf++) {
        #pragma unroll
        for (int nf = 0; nf < 4; nf++) {
            int col = col0 + wn0 + nf * 8 + tig * 2;
            float bx = bias[col], by = bias[col + 1];
            float v0 = acc[mf][nf][0] + bx;
            float v1 = acc[mf][nf][1] + by;
            float v2 = acc[mf][nf][2] + bx;
            float v3 = acc[mf][nf][3] + by;
            if (act == 1) {
                v0 = 0.5f * v0 * (1.f + erff(v0 * 0.70710678118f));
                v1 = 0.5f * v1 * (1.f + erff(v1 * 0.70710678118f));
                v2 = 0.5f * v2 * (1.f + erff(v2 * 0.70710678118f));
                v3 = 0.5f * v3 * (1.f + erff(v3 * 0.70710678118f));
            }
            int r = row0 + wm0 + mf * 16 + g;
            *(float2*)(C + (size_t)r * N + col) = make_float2(v0, v1);
            *(float2*)(C + (size_t)(r + 8) * N + col) = make_float2(v2, v3);
        }
    }
}

// ---------------- Tensor-core flash attention ----------------
// grid (B*NH, S/64), 128 threads = 4 warps, each warp owns 16 query rows.
// S = Q K^T via mma tf32 (B frag gathered from row-major Ks by index swap),
// online softmax on accumulator layout, P (tf32) reuses Ks buffer, O += P V via mma.
#define ALD 68

__global__ __launch_bounds__(128) void attention_tc(
    const float* __restrict__ Q, const float* __restrict__ K,
    const float* __restrict__ V, float* __restrict__ O,
    const void* __restrict__ temp_ptr)
{
    __shared__ float Ks[64][ALD];   // [key][d]; reused as P[q][key]
    __shared__ float Vs[64][ALD];   // [key][d]

    int bh = blockIdx.x;
    int b = bh >> 3, h = bh & 7;
    int tid = threadIdx.x, lane = tid & 31, warp = tid >> 5;
    int g = lane >> 2, tig = lane & 3;
    int qr = blockIdx.y * 64 + warp * 16;   // warp's first query row

    float scale = 0.125f / read_temp(temp_ptr);

    // Q fragments (tf32, pre-scaled), held for whole kernel
    unsigned qf[8][4];
    {
        const float* Qb = Q + ((size_t)(b * Sdim + qr)) * Edim + h * Ddim;
        #pragma unroll
        for (int ks = 0; ks < 8; ks++) {
            qf[ks][0] = f2tf32(Qb[(size_t)g * Edim + ks * 8 + tig] * scale);
            qf[ks][1] = f2tf32(Qb[(size_t)(g + 8) * Edim + ks * 8 + tig] * scale);
            qf[ks][2] = f2tf32(Qb[(size_t)g * Edim + ks * 8 + tig + 4] * scale);
            qf[ks][3] = f2tf32(Qb[(size_t)(g + 8) * Edim + ks * 8 + tig + 4] * scale);
        }
    }

    float oacc[8][4];
    #pragma unroll
    for (int nf = 0; nf < 8; nf++)
        #pragma unroll
        for (int r = 0; r < 4; r++) oacc[nf][r] = 0.f;

    float m_lo = -1e30f, m_hi = -1e30f, l_lo = 0.f, l_hi = 0.f;

    for (int kt = 0; kt < Sdim / 64; kt++) {
        // stage K and V tiles (row-major [key][d], tf32-rounded)
        #pragma unroll
        for (int it = 0; it < 8; it++) {
            int idx = tid + it * 128;
            int r = idx >> 4, c4 = idx & 15;
            size_t base = ((size_t)(b * Sdim + kt * 64 + r)) * Edim + h * Ddim + c4 * 4;
            float4 kv = *(const float4*)(K + base);
            float4 vv = *(const float4*)(V + base);
            kv.x = tf32f(kv.x); kv.y = tf32f(kv.y); kv.z = tf32f(kv.z); kv.w = tf32f(kv.w);
            vv.x = tf32f(vv.x); vv.y = tf32f(vv.y); vv.z = tf32f(vv.z); vv.w = tf32f(vv.w);
            *(float4*)&Ks[r][c4 * 4] = kv;
            *(float4*)&Vs[r][c4 * 4] = vv;
        }
        __syncthreads();

        // S = Q @ K^T : B[k=d][n=key] gathered from Ks[key][d]
        float sacc[8][4];
        #pragma unroll
        for (int nf = 0; nf < 8; nf++) {
            #pragma unroll
            for (int r = 0; r < 4; r++) sacc[nf][r] = 0.f;
            int krow = nf * 8 + g;   // key index (n)
            #pragma unroll
            for (int ks = 0; ks < 8; ks++) {
                unsigned b0 = __float_as_uint(Ks[krow][ks * 8 + tig]);
                unsigned b1 = __float_as_uint(Ks[krow][ks * 8 + tig + 4]);
                MMA_TF32(sacc[nf], qf[ks], b0, b1);
            }
        }
        __syncthreads();   // all warps done reading Ks -> safe to overwrite with P

        // online softmax on accumulator layout (rows g and g+8)
        float mx_lo = -1e30f, mx_hi = -1e30f;
        #pragma unroll
        for (int nf = 0; nf < 8; nf++) {
            mx_lo = fmaxf(mx_lo, fmaxf(sacc[nf][0], sacc[nf][1]));
            mx_hi = fmaxf(mx_hi, fmaxf(sacc[nf][2], sacc[nf][3]));
        }
        mx_lo = fmaxf(mx_lo, __shfl_xor_sync(0xffffffffu, mx_lo, 1));
        mx_lo = fmaxf(mx_lo, __shfl_xor_sync(0xffffffffu, mx_lo, 2));
        mx_hi = fmaxf(mx_hi, __shfl_xor_sync(0xffffffffu, mx_hi, 1));
        mx_hi = fmaxf(mx_hi, __shfl_xor_sync(0xffffffffu, mx_hi, 2));

        float nm_lo = fmaxf(m_lo, mx_lo), nm_hi = fmaxf(m_hi, mx_hi);
        float corr_lo = __expf(m_lo - nm_lo), corr_hi = __expf(m_hi - nm_hi);
        m_lo = nm_lo; m_hi = nm_hi;

        float rs_lo = 0.f, rs_hi = 0.f;
        int prow = warp * 16 + g;
        #pragma unroll
        for (int nf = 0; nf < 8; nf++) {
            float p0 = __expf(sacc[nf][0] - nm_lo);
            float p1 = __expf(sacc[nf][1] - nm_lo);
            float p2 = __expf(sacc[nf][2] - nm_hi);
            float p3 = __expf(sacc[nf][3] - nm_hi);
            rs_lo += p0 + p1;
            rs_hi += p2 + p3;
            int pc = nf * 8 + 2 * tig;
            Ks[prow][pc]     = tf32f(p0);
            Ks[prow][pc + 1] = tf32f(p1);
            Ks[prow + 8][pc]     = tf32f(p2);
            Ks[prow + 8][pc + 1] = tf32f(p3);
        }
        rs_lo += __shfl_xor_sync(0xffffffffu, rs_lo, 1);
        rs_lo += __shfl_xor_sync(0xffffffffu, rs_lo, 2);
        rs_hi += __shfl_xor_sync(0xffffffffu, rs_hi, 1);
        rs_hi += __shfl_xor_sync(0xffffffffu, rs_hi, 2);
        l_lo = l_lo * corr_lo + rs_lo;
        l_hi = l_hi * corr_hi + rs_hi;

        #pragma unroll
        for (int nf = 0; nf < 8; nf++) {
            oacc[nf][0] *= corr_lo; oacc[nf][1] *= corr_lo;
            oacc[nf][2] *= corr_hi; oacc[nf][3] *= corr_hi;
        }
        __syncwarp();   // warp's own P rows written before reading them back

        // O += P @ V : A from P (own rows), B[k=key][n=d] = Vs[key][d]
        #pragma unroll
        for (int ks2 = 0; ks2 < 8; ks2++) {
            unsigned af[4];
            af[0] = __float_as_uint(Ks[prow][ks2 * 8 + tig]);
            af[1] = __float_as_uint(Ks[prow + 8][ks2 * 8 + tig]);
            af[2] = __float_as_uint(Ks[prow][ks2 * 8 + tig + 4]);
            af[3] = __float_as_uint(Ks[prow + 8][ks2 * 8 + tig + 4]);
            #pragma unroll
            for (int nf = 0; nf < 8; nf++) {
                unsigned b0 = __float_as_uint(Vs[ks2 * 8 + tig][nf * 8 + g]);
                unsigned b1 = __float_as_uint(Vs[ks2 * 8 + tig + 4][nf * 8 + g]);
                MMA_TF32(oacc[nf], af, b0, b1);
            }
        }
        __syncthreads();   // before next stage overwrites Ks/Vs
    }

    float inv_lo = 1.f / l_lo, inv_hi = 1.f / l_hi;
    #pragma unroll
    for (int nf = 0; nf < 8; nf++) {
        int col = h * Ddim + nf * 8 + 2 * tig;
        *(float2*)(O + ((size_t)(b * Sdim + qr + g)) * Edim + col) =
            make_float2(oacc[nf][0] * inv_lo, oacc[nf][1] * inv_lo);
        *(float2*)(O + ((size_t)(b * Sdim + qr + g + 8)) * Edim + col) =
            make_float2(oacc[nf][2] * inv_hi, oacc[nf][3] * inv_hi);
    }
}

// ---------------- out = LayerNorm(a + b) * scale + bias ----------------
__global__ __launch_bounds__(256) void add_ln_kernel(
    const float* __restrict__ a, const float* __restrict__ b,
    const float* __restrict__ scale, const float* __restrict__ bias,
    float* __restrict__ out)
{
    __shared__ float red[256];
    int t = threadIdx.x;
    size_t base = (size_t)blockIdx.x * Edim;

    float x0 = a[base + t] + b[base + t];
    float x1 = a[base + 256 + t] + b[base + 256 + t];

    float mu = block_sum_256(x0 + x1, red) * (1.f / Edim);
    float d0 = x0 - mu, d1 = x1 - mu;
    float var = block_sum_256(d0 * d0 + d1 * d1, red) * (1.f / Edim);
    float r = rsqrtf(var + 1e-5f);

    out[base + t]       = d0 * r * scale[t]       + bias[t];
    out[base + 256 + t] = d1 * r * scale[256 + t] + bias[256 + t];
}

// ---------------- gate + mix + LayerNorm ----------------
__global__ __launch_bounds__(256) void gate_mix_ln_kernel(
    const float* __restrict__ x, const float* __restrict__ xc,
    const float* __restrict__ gw, const float* __restrict__ gb,
    const float* __restrict__ scale, const float* __restrict__ bias,
    float* __restrict__ out)
{
    __shared__ float red[256];
    int t = threadIdx.x;
    size_t base = (size_t)blockIdx.x * Edim;

    float x0 = x[base + t],        x1 = x[base + 256 + t];
    float c0 = xc[base + t],       c1 = xc[base + 256 + t];

    float l0 = x0 * gw[t * 2]             + x1 * gw[(256 + t) * 2]
             + c0 * gw[(512 + t) * 2]     + c1 * gw[(768 + t) * 2];
    float l1 = x0 * gw[t * 2 + 1]         + x1 * gw[(256 + t) * 2 + 1]
             + c0 * gw[(512 + t) * 2 + 1] + c1 * gw[(768 + t) * 2 + 1];

    l0 = block_sum_256(l0, red) + gb[0];
    l1 = block_sum_256(l1, red) + gb[1];

    float mx = fmaxf(l0, l1);
    float e0 = __expf(l0 - mx), e1 = __expf(l1 - mx);
    float g0 = e0 / (e0 + e1), g1 = 1.f - g0;

    float m0 = x0 * g0 + c0 * g1;
    float m1 = x1 * g0 + c1 * g1;

    float mu = block_sum_256(m0 + m1, red) * (1.f / Edim);
    float d0 = m0 - mu, d1 = m1 - mu;
    float var = block_sum_256(d0 * d0 + d1 * d1, red) * (1.f / Edim);
    float r = rsqrtf(var + 1e-5f);

    out[base + t]       = d0 * r * scale[t]       + bias[t];
    out[base + 256 + t] = d1 * r * scale[256 + t] + bias[256 + t];
}

// ---------------- host side ----------------
static void launch_gemm(const float* A, const float* W, const float* bias, float* C,
                        int M, int N, int K, int act)
{
    dim3 grid(N / GBN, M / GBM);
    gemm_tf32<<<grid, 256>>>(A, W, bias, C, M, N, K, act);
}

extern "C" void kernel_launch(void* const* d_in, const int* in_sizes, int n_in,
                              void* d_out, int out_size)
{
    const float* body_feats = (const float*)d_in[0];
    const float* limb_feats = (const float*)d_in[1];
    const float* qw = (const float*)d_in[2];
    const float* qb = (const float*)d_in[3];
    const float* kw = (const float*)d_in[4];
    const float* kb = (const float*)d_in[5];
    const float* vw = (const float*)d_in[6];
    const float* vb = (const float*)d_in[7];
    const float* ow = (const float*)d_in[8];
    const float* ob = (const float*)d_in[9];
    const float* w1 = (const float*)d_in[10];
    const float* b1 = (const float*)d_in[11];
    const float* w2 = (const float*)d_in[12];
    const float* b2 = (const float*)d_in[13];
    const float* ns = (const float*)d_in[14];
    const float* nb = (const float*)d_in[15];
    const float* gw = (const float*)d_in[16];
    const float* gb = (const float*)d_in[17];
    const void*  temp = d_in[18];

    float *q, *k, *v, *attn, *proj, *body1, *limb1, *bcross, *lcross, *body2, *limb2, *mid;
    cudaGetSymbolAddress((void**)&q, g_q);
    cudaGetSymbolAddress((void**)&k, g_k);
    cudaGetSymbolAddress((void**)&v, g_v);
    cudaGetSymbolAddress((void**)&attn, g_attn);
    cudaGetSymbolAddress((void**)&proj, g_proj);
    cudaGetSymbolAddress((void**)&body1, g_body1);
    cudaGetSymbolAddress((void**)&limb1, g_limb1);
    cudaGetSymbolAddress((void**)&bcross, g_bcross);
    cudaGetSymbolAddress((void**)&lcross, g_lcross);
    cudaGetSymbolAddress((void**)&body2, g_body2);
    cudaGetSymbolAddress((void**)&limb2, g_limb2);
    cudaGetSymbolAddress((void**)&mid, g_mid);

    float* out_body = (float*)d_out;
    float* out_limb = (float*)d_out + (size_t)NTOK * Edim;

    const int EE = Edim * Edim;
    dim3 agrid(Bdim * NHdim, Sdim / 64);

    // ---- self attention: body (i=0) -> body1, limb (i=1) -> limb1 ----
    for (int s = 0; s < 2; s++) {
        int i = s;
        const float* xin = (s == 0) ? body_feats : limb_feats;
        float* dst = (s == 0) ? body1 : limb1;
        int nidx = (s == 0) ? 0 : 3;

        launch_gemm(xin, qw + (size_t)i * EE, qb + i * Edim, q, NTOK, Edim, Edim, 0);
        launch_gemm(xin, kw + (size_t)i * EE, kb + i * Edim, k, NTOK, Edim, Edim, 0);
        launch_gemm(xin, vw + (size_t)i * EE, vb + i * Edim, v, NTOK, Edim, Edim, 0);
        attention_tc<<<agrid, 128>>>(q, k, v, attn, temp);
        launch_gemm(attn, ow + (size_t)i * EE, ob + i * Edim, proj, NTOK, Edim, Edim, 0);
        add_ln_kernel<<<NTOK, 256>>>(xin, proj, ns + nidx * Edim, nb + nidx * Edim, dst);
    }

    // ---- cross attention ----
    for (int s = 0; s < 2; s++) {
        int i = 2 + s;
        const float* qx = (s == 0) ? body1 : limb1;
        const float* kvx = (s == 0) ? limb1 : body1;
        float* dst = (s == 0) ? bcross : lcross;

        launch_gemm(qx,  qw + (size_t)i * EE, qb + i * Edim, q, NTOK, Edim, Edim, 0);
        launch_gemm(kvx, kw + (size_t)i * EE, kb + i * Edim, k, NTOK, Edim, Edim, 0);
        launch_gemm(kvx, vw + (size_t)i * EE, vb + i * Edim, v, NTOK, Edim, Edim, 0);
        attention_tc<<<agrid, 128>>>(q, k, v, attn, temp);
        launch_gemm(attn, ow + (size_t)i * EE, ob + i * Edim, dst, NTOK, Edim, Edim, 0);
    }

    // ---- gates + mix + LN (norm index 1 for BOTH streams, faithful to reference) ----
    gate_mix_ln_kernel<<<NTOK, 256>>>(body1, bcross, gw, gb, ns + 1 * Edim, nb + 1 * Edim, body2);
    gate_mix_ln_kernel<<<NTOK, 256>>>(limb1, lcross, gw, gb, ns + 1 * Edim, nb + 1 * Edim, limb2);

    // ---- FFN + final LN ----
    launch_gemm(body2, w1, b1, mid, NTOK, E4, Edim, 1);
    launch_gemm(mid, w2, b2, proj, NTOK, Edim, E4, 0);
    add_ln_kernel<<<NTOK, 256>>>(body2, proj, ns + 2 * Edim, nb + 2 * Edim, out_body);

    launch_gemm(limb2, w1 + (size_t)Edim * E4, b1 + E4, mid, NTOK, E4, Edim, 1);
    launch_gemm(mid, w2 + (size_t)E4 * Edim, b2 + Edim, proj, NTOK, Edim, E4, 0);
    add_ln_kernel<<<NTOK, 256>>>(limb2, proj, ns + 5 * Edim, nb + 5 * Edim, out_limb);
}

// round 4
// speedup vs baseline: 4.9119x; 1.5116x over previous
#include <cuda_runtime.h>
#include <cuda_bf16.h>
#include <math.h>

// Problem constants
#define Bdim 4
#define Sdim 1024
#define Edim 512
#define NHdim 8
#define Ddim 64
#define NTOK (Bdim * Sdim)        // 4096
#define E4 (4 * Edim)             // 2048

// ---------------- scratch (device globals; allocation-free) ----------------
__device__ float g_q[NTOK * Edim];
__device__ float g_k[NTOK * Edim];
__device__ float g_v[NTOK * Edim];
__device__ float g_q2[NTOK * Edim];
__device__ float g_k2[NTOK * Edim];
__device__ float g_v2[NTOK * Edim];
__device__ float g_attn[NTOK * Edim];
__device__ float g_attn2[NTOK * Edim];
__device__ float g_proj[NTOK * Edim];
__device__ float g_proj2[NTOK * Edim];
__device__ float g_body1[NTOK * Edim];
__device__ float g_limb1[NTOK * Edim];
__device__ float g_bcross[NTOK * Edim];
__device__ float g_lcross[NTOK * Edim];
__device__ float g_body2[NTOK * Edim];
__device__ float g_limb2[NTOK * Edim];
__device__ float g_mid[NTOK * E4];
__device__ float g_mid2[NTOK * E4];

// ---------------- helpers ----------------
__device__ __forceinline__ float read_temp(const void* p) {
    int iv = *(const int*)p;
    float fv = __int_as_float(iv);
    if (iv > 0 && iv < 0x00800000) return (float)iv;  // int bit pattern
    return fv;
}

__device__ __forceinline__ unsigned f2tf32(float f) {
    unsigned u;
    asm("cvt.rna.tf32.f32 %0, %1;" : "=r"(u) : "f"(f));
    return u;
}

__device__ __forceinline__ void cp16(void* dst, const void* src) {
    unsigned d = (unsigned)__cvta_generic_to_shared(dst);
    asm volatile("cp.async.cg.shared.global [%0], [%1], 16;\n" :: "r"(d), "l"(src));
}
__device__ __forceinline__ void cp_commit() {
    asm volatile("cp.async.commit_group;\n");
}
template<int N> __device__ __forceinline__ void cp_wait() {
    asm volatile("cp.async.wait_group %0;\n" :: "n"(N));
}

__device__ __forceinline__ float block_sum_256(float v, float* red) {
    int t = threadIdx.x;
    red[t] = v;
    __syncthreads();
    #pragma unroll
    for (int s = 128; s > 0; s >>= 1) {
        if (t < s) red[t] += red[t + s];
        __syncthreads();
    }
    float r = red[0];
    __syncthreads();
    return r;
}

#define MMA_TF32(ACC, AF, B0, B1)                                              \
    asm volatile(                                                              \
        "mma.sync.aligned.m16n8k8.row.col.f32.tf32.tf32.f32 "                  \
        "{%0,%1,%2,%3}, {%4,%5,%6,%7}, {%8,%9}, {%0,%1,%2,%3};\n"              \
        : "+f"((ACC)[0]), "+f"((ACC)[1]), "+f"((ACC)[2]), "+f"((ACC)[3])       \
        : "r"((AF)[0]), "r"((AF)[1]), "r"((AF)[2]), "r"((AF)[3]),              \
          "r"(B0), "r"(B1))

// ---------------- batched TF32 GEMM: C[M,N] = A @ W + bias (+opt GELU) ----------------
// 128x128x32 tile, 256 thr = 8 warps (4M x 2N), warp tile 32x64, double-buffered cp.async.
// smem per buffer: A 128x36, B 32x136 floats. Total dyn smem = 2*8960 floats = 71680 B.
struct GemmB { const float* A; const float* W; const float* bias; float* C; };
struct GemmB6 { GemmB g[6]; };

#define GSM_BUF 8960
#define GLA 36
#define GLB 136

__global__ __launch_bounds__(256) void gemm_tc(
    GemmB6 batch, int M, int N, int K, int act)
{
    extern __shared__ float sm[];
    GemmB gp = batch.g[blockIdx.z];
    const float* __restrict__ A = gp.A;
    const float* __restrict__ W = gp.W;

    int tid = threadIdx.x;
    int lane = tid & 31;
    int warp = tid >> 5;
    int g = lane >> 2;
    int tig = lane & 3;

    int row0 = blockIdx.y * 128;
    int col0 = blockIdx.x * 128;
    int wm0 = (warp >> 1) * 32;
    int wn0 = (warp & 1) * 64;

    float acc[2][8][4];
    #pragma unroll
    for (int mf = 0; mf < 2; mf++)
        #pragma unroll
        for (int nf = 0; nf < 8; nf++)
            #pragma unroll
            for (int r = 0; r < 4; r++) acc[mf][nf][r] = 0.f;

    // staging indices
    int a_r = 0, a_c4 = 0, b_k = 0, b_c4 = 0;
    a_r = tid >> 3; a_c4 = tid & 7;          // + it*32 rows
    b_k = tid >> 5; b_c4 = tid & 31;         // + it*8 k-rows

    int nkt = K / 32;

    // stage tile 0
    {
        float* as = sm;
        float* bs = sm + 128 * GLA;
        #pragma unroll
        for (int it = 0; it < 4; it++)
            cp16(as + (a_r + it * 32) * GLA + a_c4 * 4,
                 A + (size_t)(row0 + a_r + it * 32) * K + a_c4 * 4);
        #pragma unroll
        for (int it = 0; it < 4; it++)
            cp16(bs + (b_k + it * 8) * GLB + b_c4 * 4,
                 W + (size_t)(b_k + it * 8) * N + col0 + b_c4 * 4);
        cp_commit();
    }

    for (int kt = 0; kt < nkt; kt++) {
        if (kt + 1 < nkt) {
            int k0 = (kt + 1) * 32;
            float* as = sm + ((kt + 1) & 1) * GSM_BUF;
            float* bs = as + 128 * GLA;
            #pragma unroll
            for (int it = 0; it < 4; it++)
                cp16(as + (a_r + it * 32) * GLA + a_c4 * 4,
                     A + (size_t)(row0 + a_r + it * 32) * K + k0 + a_c4 * 4);
            #pragma unroll
            for (int it = 0; it < 4; it++)
                cp16(bs + (b_k + it * 8) * GLB + b_c4 * 4,
                     W + (size_t)(k0 + b_k + it * 8) * N + col0 + b_c4 * 4);
            cp_commit();
            cp_wait<1>();
        } else {
            cp_wait<0>();
        }
        __syncthreads();

        const float* as = sm + (kt & 1) * GSM_BUF;
        const float* bs = as + 128 * GLA;

        #pragma unroll
        for (int ks = 0; ks < 4; ks++) {
            int kk = ks * 8;
            unsigned a_frag[2][4];
            #pragma unroll
            for (int mf = 0; mf < 2; mf++) {
                int rb = wm0 + mf * 16;
                a_frag[mf][0] = __float_as_uint(as[(rb + g) * GLA + kk + tig]);
                a_frag[mf][1] = __float_as_uint(as[(rb + g + 8) * GLA + kk + tig]);
                a_frag[mf][2] = __float_as_uint(as[(rb + g) * GLA + kk + tig + 4]);
                a_frag[mf][3] = __float_as_uint(as[(rb + g + 8) * GLA + kk + tig + 4]);
            }
            unsigned b_frag[8][2];
            #pragma unroll
            for (int nf = 0; nf < 8; nf++) {
                int c = wn0 + nf * 8 + g;
                b_frag[nf][0] = __float_as_uint(bs[(kk + tig) * GLB + c]);
                b_frag[nf][1] = __float_as_uint(bs[(kk + tig + 4) * GLB + c]);
            }
            #pragma unroll
            for (int mf = 0; mf < 2; mf++)
                #pragma unroll
                for (int nf = 0; nf < 8; nf++)
                    MMA_TF32(acc[mf][nf], a_frag[mf], b_frag[nf][0], b_frag[nf][1]);
        }
        __syncthreads();
    }

    const float* bias = gp.bias;
    float* C = gp.C;
    #pragma unroll
    for (int mf = 0; mf < 2; mf++) {
        #pragma unroll
        for (int nf = 0; nf < 8; nf++) {
            int col = col0 + wn0 + nf * 8 + tig * 2;
            float bx = bias[col], by = bias[col + 1];
            float v0 = acc[mf][nf][0] + bx;
            float v1 = acc[mf][nf][1] + by;
            float v2 = acc[mf][nf][2] + bx;
            float v3 = acc[mf][nf][3] + by;
            if (act == 1) {
                v0 = 0.5f * v0 * (1.f + erff(v0 * 0.70710678118f));
                v1 = 0.5f * v1 * (1.f + erff(v1 * 0.70710678118f));
                v2 = 0.5f * v2 * (1.f + erff(v2 * 0.70710678118f));
                v3 = 0.5f * v3 * (1.f + erff(v3 * 0.70710678118f));
            }
            int r = row0 + wm0 + mf * 16 + g;
            *(float2*)(C + (size_t)r * N + col) = make_float2(v0, v1);
            *(float2*)(C + (size_t)(r + 8) * N + col) = make_float2(v2, v3);
        }
    }
}

// ---------------- batched tensor-core flash attention ----------------
// grid (B*NH, S/64, 2), 128 thr = 4 warps, each warp 16 query rows.
// Double-buffered cp.async K/V tiles; P stays in registers (shfl relayout).
// Ks ld=68 (S-gather conflict-free), Vs ld=72 (PV-gather conflict-free).
struct AttnB { const float* Q; const float* K; const float* V; float* O; };
struct AttnB2 { AttnB a[2]; };

#define KLD 68
#define VLD 72
// smem: Ks[2][64][68] then Vs[2][64][72] = 8704 + 9216 floats = 71680 B

__global__ __launch_bounds__(128) void attention_tc(
    AttnB2 batch, const void* __restrict__ temp_ptr)
{
    extern __shared__ float sm[];
    AttnB ap = batch.a[blockIdx.z];
    const float* __restrict__ Q = ap.Q;
    const float* __restrict__ K = ap.K;
    const float* __restrict__ V = ap.V;

    int bh = blockIdx.x;
    int b = bh >> 3, h = bh & 7;
    int tid = threadIdx.x, lane = tid & 31, warp = tid >> 5;
    int g = lane >> 2, tig = lane & 3;
    int qr = blockIdx.y * 64 + warp * 16;

    float scale = 0.125f / read_temp(temp_ptr);

    // Q fragments (tf32, pre-scaled)
    unsigned qf[8][4];
    {
        const float* Qb = Q + ((size_t)(b * Sdim + qr)) * Edim + h * Ddim;
        #pragma unroll
        for (int ks = 0; ks < 8; ks++) {
            qf[ks][0] = f2tf32(Qb[(size_t)g * Edim + ks * 8 + tig] * scale);
            qf[ks][1] = f2tf32(Qb[(size_t)(g + 8) * Edim + ks * 8 + tig] * scale);
            qf[ks][2] = f2tf32(Qb[(size_t)g * Edim + ks * 8 + tig + 4] * scale);
            qf[ks][3] = f2tf32(Qb[(size_t)(g + 8) * Edim + ks * 8 + tig + 4] * scale);
        }
    }

    float oacc[8][4];
    #pragma unroll
    for (int nf = 0; nf < 8; nf++)
        #pragma unroll
        for (int r = 0; r < 4; r++) oacc[nf][r] = 0.f;

    float m_lo = -1e30f, m_hi = -1e30f, l_lo = 0.f, l_hi = 0.f;

    int st_r = tid >> 4;      // + it*8 rows
    int st_c4 = tid & 15;

    // stage tile 0
    {
        float* ks_ = sm;
        float* vs_ = sm + 8704;
        #pragma unroll
        for (int it = 0; it < 8; it++) {
            int r = st_r + it * 8;
            size_t base = ((size_t)(b * Sdim + r)) * Edim + h * Ddim + st_c4 * 4;
            cp16(ks_ + r * KLD + st_c4 * 4, K + base);
            cp16(vs_ + r * VLD + st_c4 * 4, V + base);
        }
        cp_commit();
    }

    const int NKT = Sdim / 64;
    for (int kt = 0; kt < NKT; kt++) {
        if (kt + 1 < NKT) {
            float* ks_ = sm + ((kt + 1) & 1) * 4352;
            float* vs_ = sm + 8704 + ((kt + 1) & 1) * 4608;
            #pragma unroll
            for (int it = 0; it < 8; it++) {
                int r = st_r + it * 8;
                size_t base = ((size_t)(b * Sdim + (kt + 1) * 64 + r)) * Edim + h * Ddim + st_c4 * 4;
                cp16(ks_ + r * KLD + st_c4 * 4, K + base);
                cp16(vs_ + r * VLD + st_c4 * 4, V + base);
            }
            cp_commit();
            cp_wait<1>();
        } else {
            cp_wait<0>();
        }
        __syncthreads();

        const float* ks_ = sm + (kt & 1) * 4352;
        const float* vs_ = sm + 8704 + (kt & 1) * 4608;

        // S = Q @ K^T
        float sacc[8][4];
        #pragma unroll
        for (int nf = 0; nf < 8; nf++) {
            #pragma unroll
            for (int r = 0; r < 4; r++) sacc[nf][r] = 0.f;
            int krow = nf * 8 + g;
            #pragma unroll
            for (int ks = 0; ks < 8; ks++) {
                unsigned b0 = __float_as_uint(ks_[krow * KLD + ks * 8 + tig]);
                unsigned b1 = __float_as_uint(ks_[krow * KLD + ks * 8 + tig + 4]);
                MMA_TF32(sacc[nf], qf[ks], b0, b1);
            }
        }

        // online softmax (register-only)
        float mx_lo = -1e30f, mx_hi = -1e30f;
        #pragma unroll
        for (int nf = 0; nf < 8; nf++) {
            mx_lo = fmaxf(mx_lo, fmaxf(sacc[nf][0], sacc[nf][1]));
            mx_hi = fmaxf(mx_hi, fmaxf(sacc[nf][2], sacc[nf][3]));
        }
        mx_lo = fmaxf(mx_lo, __shfl_xor_sync(0xffffffffu, mx_lo, 1));
        mx_lo = fmaxf(mx_lo, __shfl_xor_sync(0xffffffffu, mx_lo, 2));
        mx_hi = fmaxf(mx_hi, __shfl_xor_sync(0xffffffffu, mx_hi, 1));
        mx_hi = fmaxf(mx_hi, __shfl_xor_sync(0xffffffffu, mx_hi, 2));

        float nm_lo = fmaxf(m_lo, mx_lo), nm_hi = fmaxf(m_hi, mx_hi);
        float corr_lo = __expf(m_lo - nm_lo), corr_hi = __expf(m_hi - nm_hi);
        m_lo = nm_lo; m_hi = nm_hi;

        float rs_lo = 0.f, rs_hi = 0.f;
        #pragma unroll
        for (int nf = 0; nf < 8; nf++) {
            sacc[nf][0] = __expf(sacc[nf][0] - nm_lo);
            sacc[nf][1] = __expf(sacc[nf][1] - nm_lo);
            sacc[nf][2] = __expf(sacc[nf][2] - nm_hi);
            sacc[nf][3] = __expf(sacc[nf][3] - nm_hi);
            rs_lo += sacc[nf][0] + sacc[nf][1];
            rs_hi += sacc[nf][2] + sacc[nf][3];
        }
        rs_lo += __shfl_xor_sync(0xffffffffu, rs_lo, 1);
        rs_lo += __shfl_xor_sync(0xffffffffu, rs_lo, 2);
        rs_hi += __shfl_xor_sync(0xffffffffu, rs_hi, 1);
        rs_hi += __shfl_xor_sync(0xffffffffu, rs_hi, 2);
        l_lo = l_lo * corr_lo + rs_lo;
        l_hi = l_hi * corr_hi + rs_hi;

        #pragma unroll
        for (int nf = 0; nf < 8; nf++) {
            oacc[nf][0] *= corr_lo; oacc[nf][1] *= corr_lo;
            oacc[nf][2] *= corr_hi; oacc[nf][3] *= corr_hi;
        }

        // O += P @ V : A-fragments built from sacc via shfl relayout
        int lane0 = 4 * g + (tig >> 1);
        int lane2 = lane0 + 2;
        bool odd = (tig & 1);
        #pragma unroll
        for (int ks2 = 0; ks2 < 8; ks2++) {
            float w00 = __shfl_sync(0xffffffffu, sacc[ks2][0], lane0);
            float w01 = __shfl_sync(0xffffffffu, sacc[ks2][1], lane0);
            float w10 = __shfl_sync(0xffffffffu, sacc[ks2][2], lane0);
            float w11 = __shfl_sync(0xffffffffu, sacc[ks2][3], lane0);
            float w20 = __shfl_sync(0xffffffffu, sacc[ks2][0], lane2);
            float w21 = __shfl_sync(0xffffffffu, sacc[ks2][1], lane2);
            float w30 = __shfl_sync(0xffffffffu, sacc[ks2][2], lane2);
            float w31 = __shfl_sync(0xffffffffu, sacc[ks2][3], lane2);
            unsigned af[4];
            af[0] = __float_as_uint(odd ? w01 : w00);
            af[1] = __float_as_uint(odd ? w11 : w10);
            af[2] = __float_as_uint(odd ? w21 : w20);
            af[3] = __float_as_uint(odd ? w31 : w30);
            #pragma unroll
            for (int nf = 0; nf < 8; nf++) {
                unsigned b0 = __float_as_uint(vs_[(ks2 * 8 + tig) * VLD + nf * 8 + g]);
                unsigned b1 = __float_as_uint(vs_[(ks2 * 8 + tig + 4) * VLD + nf * 8 + g]);
                MMA_TF32(oacc[nf], af, b0, b1);
            }
        }
        __syncthreads();
    }

    float inv_lo = 1.f / l_lo, inv_hi = 1.f / l_hi;
    float* O = ap.O;
    #pragma unroll
    for (int nf = 0; nf < 8; nf++) {
        int col = h * Ddim + nf * 8 + 2 * tig;
        *(float2*)(O + ((size_t)(b * Sdim + qr + g)) * Edim + col) =
            make_float2(oacc[nf][0] * inv_lo, oacc[nf][1] * inv_lo);
        *(float2*)(O + ((size_t)(b * Sdim + qr + g + 8)) * Edim + col) =
            make_float2(oacc[nf][2] * inv_hi, oacc[nf][3] * inv_hi);
    }
}

// ---------------- out = LayerNorm(a + b) * scale + bias ----------------
__global__ __launch_bounds__(256) void add_ln_kernel(
    const float* __restrict__ a, const float* __restrict__ b,
    const float* __restrict__ scale, const float* __restrict__ bias,
    float* __restrict__ out)
{
    __shared__ float red[256];
    int t = threadIdx.x;
    size_t base = (size_t)blockIdx.x * Edim;

    float x0 = a[base + t] + b[base + t];
    float x1 = a[base + 256 + t] + b[base + 256 + t];

    float mu = block_sum_256(x0 + x1, red) * (1.f / Edim);
    float d0 = x0 - mu, d1 = x1 - mu;
    float var = block_sum_256(d0 * d0 + d1 * d1, red) * (1.f / Edim);
    float r = rsqrtf(var + 1e-5f);

    out[base + t]       = d0 * r * scale[t]       + bias[t];
    out[base + 256 + t] = d1 * r * scale[256 + t] + bias[256 + t];
}

// ---------------- gate + mix + LayerNorm ----------------
__global__ __launch_bounds__(256) void gate_mix_ln_kernel(
    const float* __restrict__ x, const float* __restrict__ xc,
    const float* __restrict__ gw, const float* __restrict__ gb,
    const float* __restrict__ scale, const float* __restrict__ bias,
    float* __restrict__ out)
{
    __shared__ float red[256];
    int t = threadIdx.x;
    size_t base = (size_t)blockIdx.x * Edim;

    float x0 = x[base + t],        x1 = x[base + 256 + t];
    float c0 = xc[base + t],       c1 = xc[base + 256 + t];

    float l0 = x0 * gw[t * 2]             + x1 * gw[(256 + t) * 2]
             + c0 * gw[(512 + t) * 2]     + c1 * gw[(768 + t) * 2];
    float l1 = x0 * gw[t * 2 + 1]         + x1 * gw[(256 + t) * 2 + 1]
             + c0 * gw[(512 + t) * 2 + 1] + c1 * gw[(768 + t) * 2 + 1];

    l0 = block_sum_256(l0, red) + gb[0];
    l1 = block_sum_256(l1, red) + gb[1];

    float mx = fmaxf(l0, l1);
    float e0 = __expf(l0 - mx), e1 = __expf(l1 - mx);
    float g0 = e0 / (e0 + e1), g1 = 1.f - g0;

    float m0 = x0 * g0 + c0 * g1;
    float m1 = x1 * g0 + c1 * g1;

    float mu = block_sum_256(m0 + m1, red) * (1.f / Edim);
    float d0 = m0 - mu, d1 = m1 - mu;
    float var = block_sum_256(d0 * d0 + d1 * d1, red) * (1.f / Edim);
    float r = rsqrtf(var + 1e-5f);

    out[base + t]       = d0 * r * scale[t]       + bias[t];
    out[base + 256 + t] = d1 * r * scale[256 + t] + bias[256 + t];
}

// ---------------- host side ----------------
#define GEMM_SMEM 71680
#define ATTN_SMEM 71680

extern "C" void kernel_launch(void* const* d_in, const int* in_sizes, int n_in,
                              void* d_out, int out_size)
{
    const float* body_feats = (const float*)d_in[0];
    const float* limb_feats = (const float*)d_in[1];
    const float* qw = (const float*)d_in[2];
    const float* qb = (const float*)d_in[3];
    const float* kw = (const float*)d_in[4];
    const float* kb = (const float*)d_in[5];
    const float* vw = (const float*)d_in[6];
    const float* vb = (const float*)d_in[7];
    const float* ow = (const float*)d_in[8];
    const float* ob = (const float*)d_in[9];
    const float* w1 = (const float*)d_in[10];
    const float* b1 = (const float*)d_in[11];
    const float* w2 = (const float*)d_in[12];
    const float* b2 = (const float*)d_in[13];
    const float* ns = (const float*)d_in[14];
    const float* nb = (const float*)d_in[15];
    const float* gw = (const float*)d_in[16];
    const float* gb = (const float*)d_in[17];
    const void*  temp = d_in[18];

    cudaFuncSetAttribute(gemm_tc, cudaFuncAttributeMaxDynamicSharedMemorySize, GEMM_SMEM);
    cudaFuncSetAttribute(attention_tc, cudaFuncAttributeMaxDynamicSharedMemorySize, ATTN_SMEM);

    float *q, *k, *v, *q2, *k2, *v2, *attn, *attn2, *proj, *proj2;
    float *body1, *limb1, *bcross, *lcross, *body2, *limb2, *mid, *mid2;
    cudaGetSymbolAddress((void**)&q, g_q);
    cudaGetSymbolAddress((void**)&k, g_k);
    cudaGetSymbolAddress((void**)&v, g_v);
    cudaGetSymbolAddress((void**)&q2, g_q2);
    cudaGetSymbolAddress((void**)&k2, g_k2);
    cudaGetSymbolAddress((void**)&v2, g_v2);
    cudaGetSymbolAddress((void**)&attn, g_attn);
    cudaGetSymbolAddress((void**)&attn2, g_attn2);
    cudaGetSymbolAddress((void**)&proj, g_proj);
    cudaGetSymbolAddress((void**)&proj2, g_proj2);
    cudaGetSymbolAddress((void**)&body1, g_body1);
    cudaGetSymbolAddress((void**)&limb1, g_limb1);
    cudaGetSymbolAddress((void**)&bcross, g_bcross);
    cudaGetSymbolAddress((void**)&lcross, g_lcross);
    cudaGetSymbolAddress((void**)&body2, g_body2);
    cudaGetSymbolAddress((void**)&limb2, g_limb2);
    cudaGetSymbolAddress((void**)&mid, g_mid);
    cudaGetSymbolAddress((void**)&mid2, g_mid2);

    float* out_body = (float*)d_out;
    float* out_limb = (float*)d_out + (size_t)NTOK * Edim;

    const size_t EE = (size_t)Edim * Edim;
    dim3 agrid(Bdim * NHdim, Sdim / 64, 2);

    // ===== self attention stage =====
    {
        GemmB6 bt;
        bt.g[0] = { body_feats, qw + 0 * EE, qb + 0 * Edim, q };
        bt.g[1] = { body_feats, kw + 0 * EE, kb + 0 * Edim, k };
        bt.g[2] = { body_feats, vw + 0 * EE, vb + 0 * Edim, v };
        bt.g[3] = { limb_feats, qw + 1 * EE, qb + 1 * Edim, q2 };
        bt.g[4] = { limb_feats, kw + 1 * EE, kb + 1 * Edim, k2 };
        bt.g[5] = { limb_feats, vw + 1 * EE, vb + 1 * Edim, v2 };
        gemm_tc<<<dim3(Edim / 128, NTOK / 128, 6), 256, GEMM_SMEM>>>(bt, NTOK, Edim, Edim, 0);
    }
    {
        AttnB2 at;
        at.a[0] = { q, k, v, attn };
        at.a[1] = { q2, k2, v2, attn2 };
        attention_tc<<<agrid, 128, ATTN_SMEM>>>(at, temp);
    }
    {
        GemmB6 bt;
        bt.g[0] = { attn,  ow + 0 * EE, ob + 0 * Edim, proj };
        bt.g[1] = { attn2, ow + 1 * EE, ob + 1 * Edim, proj2 };
        bt.g[2] = bt.g[0]; bt.g[3] = bt.g[0]; bt.g[4] = bt.g[0]; bt.g[5] = bt.g[0];
        gemm_tc<<<dim3(Edim / 128, NTOK / 128, 2), 256, GEMM_SMEM>>>(bt, NTOK, Edim, Edim, 0);
    }
    add_ln_kernel<<<NTOK, 256>>>(body_feats, proj, ns + 0 * Edim, nb + 0 * Edim, body1);
    add_ln_kernel<<<NTOK, 256>>>(limb_feats, proj2, ns + 3 * Edim, nb + 3 * Edim, limb1);

    // ===== cross attention stage =====
    {
        GemmB6 bt;
        bt.g[0] = { body1, qw + 2 * EE, qb + 2 * Edim, q };
        bt.g[1] = { limb1, kw + 2 * EE, kb + 2 * Edim, k };
        bt.g[2] = { limb1, vw + 2 * EE, vb + 2 * Edim, v };
        bt.g[3] = { limb1, qw + 3 * EE, qb + 3 * Edim, q2 };
        bt.g[4] = { body1, kw + 3 * EE, kb + 3 * Edim, k2 };
        bt.g[5] = { body1, vw + 3 * EE, vb + 3 * Edim, v2 };
        gemm_tc<<<dim3(Edim / 128, NTOK / 128, 6), 256, GEMM_SMEM>>>(bt, NTOK, Edim, Edim, 0);
    }
    {
        AttnB2 at;
        at.a[0] = { q, k, v, attn };
        at.a[1] = { q2, k2, v2, attn2 };
        attention_tc<<<agrid, 128, ATTN_SMEM>>>(at, temp);
    }
    {
        GemmB6 bt;
        bt.g[0] = { attn,  ow + 2 * EE, ob + 2 * Edim, bcross };
        bt.g[1] = { attn2, ow + 3 * EE, ob + 3 * Edim, lcross };
        bt.g[2] = bt.g[0]; bt.g[3] = bt.g[0]; bt.g[4] = bt.g[0]; bt.g[5] = bt.g[0];
        gemm_tc<<<dim3(Edim / 128, NTOK / 128, 2), 256, GEMM_SMEM>>>(bt, NTOK, Edim, Edim, 0);
    }

    // ===== gates + mix + LN (norm index 1 for BOTH streams, faithful) =====
    gate_mix_ln_kernel<<<NTOK, 256>>>(body1, bcross, gw, gb, ns + 1 * Edim, nb + 1 * Edim, body2);
    gate_mix_ln_kernel<<<NTOK, 256>>>(limb1, lcross, gw, gb, ns + 1 * Edim, nb + 1 * Edim, limb2);

    // ===== FFN + final LN =====
    {
        GemmB6 bt;
        bt.g[0] = { body2, w1, b1, mid };
        bt.g[1] = { limb2, w1 + (size_t)Edim * E4, b1 + E4, mid2 };
        bt.g[2] = bt.g[0]; bt.g[3] = bt.g[0]; bt.g[4] = bt.g[0]; bt.g[5] = bt.g[0];
        gemm_tc<<<dim3(E4 / 128, NTOK / 128, 2), 256, GEMM_SMEM>>>(bt, NTOK, E4, Edim, 1);
    }
    {
        GemmB6 bt;
        bt.g[0] = { mid,  w2, b2, proj };
        bt.g[1] = { mid2, w2 + (size_t)E4 * Edim, b2 + Edim, proj2 };
        bt.g[2] = bt.g[0]; bt.g[3] = bt.g[0]; bt.g[4] = bt.g[0]; bt.g[5] = bt.g[0];
        gemm_tc<<<dim3(Edim / 128, NTOK / 128, 2), 256, GEMM_SMEM>>>(bt, NTOK, Edim, E4, 0);
    }
    add_ln_kernel<<<NTOK, 256>>>(body2, proj, ns + 2 * Edim, nb + 2 * Edim, out_body);
    add_ln_kernel<<<NTOK, 256>>>(limb2, proj2, ns + 5 * Edim, nb + 5 * Edim, out_limb);
}